// round 9
// baseline (speedup 1.0000x reference)
#include <cuda_runtime.h>

typedef unsigned long long u64;

// Packed folded weights: {Weff[2p][r3][co], Weff[2p+1][r3][co]} as f32x2
// index: (pair*27 + r3)*32 + co
__device__ u64 g_wf2[8 * 27 * 32];
// Per-channel constant: bias*scale + beta - mean*scale
__device__ float g_cb[32];

// ---------------------------------------------------------------------------
// Prep: fold ConvTranspose taps + BN affine + pool 1/64 into packed Weff.
// Tap sets per residue r (z = 2i - 1 + k, z-offset in [0,3]):
//   T(0) = {1,2}, T(1) = {0,1,2}, T(2) = {0}
// ---------------------------------------------------------------------------
__global__ void prep_kernel(const float* __restrict__ w,
                            const float* __restrict__ bias,
                            const float* __restrict__ gamma,
                            const float* __restrict__ beta,
                            const float* __restrict__ mean,
                            const float* __restrict__ var) {
    int idx = blockIdx.x * blockDim.x + threadIdx.x;
    if (idx >= 16 * 27 * 32) return;

    int co = idx & 31;
    int r3 = (idx >> 5) % 27;
    int ci = idx / (27 * 32);
    int rd = r3 / 9, rh = (r3 / 3) % 3, rw = r3 % 3;

    const int st[3] = {1, 0, 0};
    const int en[3] = {3, 3, 1};

    const float* wb = w + ((size_t)(ci * 32 + co)) * 27;
    float s = 0.f;
    for (int kd = st[rd]; kd < en[rd]; ++kd)
        for (int kh = st[rh]; kh < en[rh]; ++kh)
            for (int kw = st[rw]; kw < en[rw]; ++kw)
                s += wb[kd * 9 + kh * 3 + kw];

    float sc = gamma[co] * rsqrtf(var[co] + 1e-5f);
    float val = s * sc * (1.f / 64.f);
    ((float*)g_wf2)[((((ci >> 1) * 27) + r3) * 32 + co) * 2 + (ci & 1)] = val;

    if (idx < 32) {
        float sc2 = gamma[idx] * rsqrtf(var[idx] + 1e-5f);
        g_cb[idx] = bias[idx] * sc2 + beta[idx] - mean[idx] * sc2;
    }
}

__device__ __forceinline__ void fma2(u64& d, u64 a, u64 b) {
    asm("fma.rn.f32x2 %0, %1, %2, %0;" : "+l"(d) : "l"(a), "l"(b));
}

// Compute one ci-pair over one staged tile; write 11 partial sums to red row.
__device__ __forceinline__ void compute_tile(const u64* __restrict__ xw,
                                             const u64* __restrict__ wp,
                                             float* __restrict__ redw,
                                             int lane) {
    u64 acc[11];
#pragma unroll
    for (int i = 0; i < 11; ++i) acc[i] = 0ull;

#pragma unroll
    for (int rr = 0; rr < 9; ++rr) {
        u64 w0 = __ldg(wp + (rr * 3 + 0) * 32);
        u64 w1 = __ldg(wp + (rr * 3 + 1) * 32);
        u64 w2 = __ldg(wp + (rr * 3 + 2) * 32);
        const ulonglong2* rp = reinterpret_cast<const ulonglong2*>(xw + rr * 24);

        u64 xv[14];
#pragma unroll
        for (int k = 0; k < 6; ++k) {
            ulonglong2 t = rp[k];
            xv[2 * k] = t.x; xv[2 * k + 1] = t.y;
        }
#pragma unroll
        for (int ow = 0; ow < 5; ++ow) {
            fma2(acc[ow], w0, xv[2 * ow]);
            fma2(acc[ow], w1, xv[2 * ow + 1]);
            fma2(acc[ow], w2, xv[2 * ow + 2]);
        }
        fma2(acc[5], w0, xv[10]);
        fma2(acc[5], w1, xv[11]);
#pragma unroll
        for (int k = 0; k < 6; ++k) {
            ulonglong2 t = rp[6 + k];
            xv[2 * k + 2] = t.x; xv[2 * k + 3] = t.y;
        }
        fma2(acc[5], w2, xv[2]);   // i = 12
#pragma unroll
        for (int ow = 6; ow < 11; ++ow) {
            fma2(acc[ow], w0, xv[2 * ow - 10]);
            fma2(acc[ow], w1, xv[2 * ow - 9]);
            fma2(acc[ow], w2, xv[2 * ow - 8]);
        }
    }

#pragma unroll
    for (int ow = 0; ow < 11; ++ow) {
        float lo, hi;
        asm("mov.b64 {%0, %1}, %2;" : "=f"(lo), "=f"(hi) : "l"(acc[ow]));
        redw[ow * 32 + lane] = lo + hi;
    }
}

// ---------------------------------------------------------------------------
// Main: 484 blocks x 256 threads; block pipelines tiles blockIdx and
// blockIdx+484 (tile = (b, od, oh)).
//   Stage: ci-pair-interleaved f32x2 tile built in registers (LDG.128 x2 ->
//   shuffle -> STS.128 x2), tile1's LDGs issued before tile0's compute.
//   Warp wid computes ci pair wid; lane = co; fma.rn.f32x2 over 11 ow accs.
// ---------------------------------------------------------------------------
__global__ __launch_bounds__(256, 2)
void conv_fused_kernel(const float* __restrict__ x, float* __restrict__ out) {
    __shared__ __align__(16) u64 xs2[2][8 * 9 * 24];   // 27648 B
    __shared__ float red[8][352];                      // 11264 B

    const int tid  = threadIdx.x;
    const int lane = tid & 31;   // co
    const int wid  = tid >> 5;   // ci pair

    // ---- staging task decode (task t: pair, rr, q) ----
    const int t0 = tid;
    const int p0 = t0 / 54, u0 = t0 - p0 * 54;
    const int rr0 = u0 / 6, q0 = u0 - rr0 * 6;
    const int so0 = 2 * p0 * 13824 + (rr0 / 3) * 576 + (rr0 % 3) * 24 + 4 * q0;
    const int df0 = (p0 * 9 + rr0) * 12 + 2 * q0;      // float4 index in xs2

    const bool h1 = (tid < 176);
    const int t1 = tid + 256;
    const int p1 = t1 / 54, u1 = t1 - p1 * 54;
    const int rr1 = u1 / 6, q1 = u1 - rr1 * 6;
    const int so1 = 2 * p1 * 13824 + (rr1 / 3) * 576 + (rr1 % 3) * 24 + 4 * q1;
    const int df1 = (p1 * 9 + rr1) * 12 + 2 * q1;

    // ---- tile decode ----
    int gw0 = blockIdx.x, gw1 = blockIdx.x + 484;
    int b0 = gw0 / 121, rem0 = gw0 - b0 * 121, od0 = rem0 / 11, oh0 = rem0 - od0 * 11;
    int b1 = gw1 / 121, rem1 = gw1 - b1 * 121, od1 = rem1 / 11, oh1 = rem1 - od1 * 11;
    const float* xb0 = x + (size_t)b0 * 221184 + (2 * od0) * 576 + (2 * oh0) * 24;
    const float* xb1 = x + (size_t)b1 * 221184 + (2 * od1) * 576 + (2 * oh1) * 24;

    const u64* wp = g_wf2 + (size_t)wid * 864 + lane;

    float4 A0, B0, A1, B1;

    // ---- prologue: stage tile 0 ----
    A0 = __ldg(reinterpret_cast<const float4*>(xb0 + so0));
    B0 = __ldg(reinterpret_cast<const float4*>(xb0 + so0 + 13824));
    if (h1) {
        A1 = __ldg(reinterpret_cast<const float4*>(xb0 + so1));
        B1 = __ldg(reinterpret_cast<const float4*>(xb0 + so1 + 13824));
    }
    {
        float4* d = reinterpret_cast<float4*>(xs2[0]);
        d[df0]     = make_float4(A0.x, B0.x, A0.y, B0.y);
        d[df0 + 1] = make_float4(A0.z, B0.z, A0.w, B0.w);
        if (h1) {
            d[df1]     = make_float4(A1.x, B1.x, A1.y, B1.y);
            d[df1 + 1] = make_float4(A1.z, B1.z, A1.w, B1.w);
        }
    }
    __syncthreads();

    // ---- issue tile1 loads, then compute tile0 (latency hidden) ----
    A0 = __ldg(reinterpret_cast<const float4*>(xb1 + so0));
    B0 = __ldg(reinterpret_cast<const float4*>(xb1 + so0 + 13824));
    if (h1) {
        A1 = __ldg(reinterpret_cast<const float4*>(xb1 + so1));
        B1 = __ldg(reinterpret_cast<const float4*>(xb1 + so1 + 13824));
    }

    compute_tile(xs2[0] + wid * 216, wp, &red[wid][0], lane);

    {
        float4* d = reinterpret_cast<float4*>(xs2[1]);
        d[df0]     = make_float4(A0.x, B0.x, A0.y, B0.y);
        d[df0 + 1] = make_float4(A0.z, B0.z, A0.w, B0.w);
        if (h1) {
            d[df1]     = make_float4(A1.x, B1.x, A1.y, B1.y);
            d[df1 + 1] = make_float4(A1.z, B1.z, A1.w, B1.w);
        }
    }
    __syncthreads();   // red(tile0) + xs2[1] ready

    // ---- store tile0 ----
#pragma unroll
    for (int it = 0; it < 2; ++it) {
        int j = tid + it * 256;
        if (j < 352) {
            float s = g_cb[j & 31];
#pragma unroll
            for (int w = 0; w < 8; ++w) s += red[w][j];
            out[((size_t)(b0 * 32 + (j & 31))) * 1331 + od0 * 121 + oh0 * 11 + (j >> 5)] = s;
        }
    }
    __syncthreads();   // red free for reuse

    // ---- compute + store tile1 ----
    compute_tile(xs2[1] + wid * 216, wp, &red[wid][0], lane);
    __syncthreads();

#pragma unroll
    for (int it = 0; it < 2; ++it) {
        int j = tid + it * 256;
        if (j < 352) {
            float s = g_cb[j & 31];
#pragma unroll
            for (int w = 0; w < 8; ++w) s += red[w][j];
            out[((size_t)(b1 * 32 + (j & 31))) * 1331 + od1 * 121 + oh1 * 11 + (j >> 5)] = s;
        }
    }
}

extern "C" void kernel_launch(void* const* d_in, const int* in_sizes, int n_in,
                              void* d_out, int out_size) {
    const float* x     = (const float*)d_in[0];
    const float* w     = (const float*)d_in[1];
    const float* bias  = (const float*)d_in[2];
    const float* gamma = (const float*)d_in[3];
    const float* beta  = (const float*)d_in[4];
    const float* mean  = (const float*)d_in[5];
    const float* var   = (const float*)d_in[6];
    float* out = (float*)d_out;

    prep_kernel<<<(16 * 27 * 32 + 255) / 256, 256>>>(w, bias, gamma, beta, mean, var);
    conv_fused_kernel<<<484, 256>>>(x, out);
}

// round 10
// speedup vs baseline: 1.0425x; 1.0425x over previous
#include <cuda_runtime.h>

typedef unsigned long long u64;

// Packed folded weights: {Weff[2p][r3][co], Weff[2p+1][r3][co]} as f32x2
// index: (pair*27 + r3)*32 + co
__device__ u64 g_wf2[8 * 27 * 32];
// Per-channel constant: bias*scale + beta - mean*scale
__device__ float g_cb[32];

// ---------------------------------------------------------------------------
// Prep: fold ConvTranspose taps + BN affine + pool 1/64 into packed Weff.
// Tap sets per residue r (z = 2i - 1 + k, z-offset in [0,3]):
//   T(0) = {1,2}, T(1) = {0,1,2}, T(2) = {0}
// ---------------------------------------------------------------------------
__global__ void prep_kernel(const float* __restrict__ w,
                            const float* __restrict__ bias,
                            const float* __restrict__ gamma,
                            const float* __restrict__ beta,
                            const float* __restrict__ mean,
                            const float* __restrict__ var) {
    int idx = blockIdx.x * blockDim.x + threadIdx.x;
    if (idx >= 16 * 27 * 32) return;

    int co = idx & 31;
    int r3 = (idx >> 5) % 27;
    int ci = idx / (27 * 32);
    int rd = r3 / 9, rh = (r3 / 3) % 3, rw = r3 % 3;

    const int st[3] = {1, 0, 0};
    const int en[3] = {3, 3, 1};

    const float* wb = w + ((size_t)(ci * 32 + co)) * 27;
    float s = 0.f;
    for (int kd = st[rd]; kd < en[rd]; ++kd)
        for (int kh = st[rh]; kh < en[rh]; ++kh)
            for (int kw = st[rw]; kw < en[rw]; ++kw)
                s += wb[kd * 9 + kh * 3 + kw];

    float sc = gamma[co] * rsqrtf(var[co] + 1e-5f);
    float val = s * sc * (1.f / 64.f);
    ((float*)g_wf2)[((((ci >> 1) * 27) + r3) * 32 + co) * 2 + (ci & 1)] = val;

    if (idx < 32) {
        float sc2 = gamma[idx] * rsqrtf(var[idx] + 1e-5f);
        g_cb[idx] = bias[idx] * sc2 + beta[idx] - mean[idx] * sc2;
    }
}

__device__ __forceinline__ void fma2(u64& d, u64 a, u64 b) {
    asm("fma.rn.f32x2 %0, %1, %2, %0;" : "+l"(d) : "l"(a), "l"(b));
}

// ---------------------------------------------------------------------------
// Main: 296 persistent blocks x 256 threads (exactly 2 blocks/SM, one wave).
// Block bid processes tiles bid, bid+296, bid+592[, bid+888] (tile=(b,od,oh)).
//   - Folded weights (27 f32x2 per ci-pair per lane) live in REGISTERS for
//     the whole kernel: zero weight loads in the steady state.
//   - x tile staged ci-pair-interleaved into double-buffered smem; next
//     tile's LDG.128s issue before current tile's compute (latency hidden).
//   - Warp wid computes ci pair wid; lane = co; streamed x (x0/x1 carry),
//     fma.rn.f32x2 over 11 ow accumulators; cross-warp reduce via smem.
// ---------------------------------------------------------------------------
__global__ __launch_bounds__(256, 2)
void conv_fused_kernel(const float* __restrict__ x, float* __restrict__ out) {
    __shared__ __align__(16) u64 xs2[2][8 * 9 * 24];   // 27648 B
    __shared__ float red[8][352];                      // 11264 B

    const int tid  = threadIdx.x;
    const int lane = tid & 31;   // co
    const int wid  = tid >> 5;   // ci pair

    // ---- staging task decode (task t: pair, rr, q), hoisted ----
    const int p0  = tid / 54, u0 = tid - p0 * 54;
    const int rr0 = u0 / 6,  q0 = u0 - rr0 * 6;
    const int so0 = 2 * p0 * 13824 + (rr0 / 3) * 576 + (rr0 % 3) * 24 + 4 * q0;
    const int df0 = (p0 * 9 + rr0) * 12 + 2 * q0;      // float4 index in xs2

    const bool h1 = (tid < 176);
    const int t1  = tid + 256;
    const int p1  = t1 / 54, u1 = t1 - p1 * 54;
    const int rr1 = u1 / 6,  q1 = u1 - rr1 * 6;
    const int so1 = 2 * p1 * 13824 + (rr1 / 3) * 576 + (rr1 % 3) * 24 + 4 * q1;
    const int df1 = (p1 * 9 + rr1) * 12 + 2 * q1;

    // ---- per-warp weights: loaded ONCE, pinned in registers ----
    u64 wr[27];
    {
        const u64* wp = g_wf2 + (size_t)wid * 864 + lane;
#pragma unroll
        for (int r = 0; r < 27; ++r) wr[r] = __ldg(wp + r * 32);
    }
    const float cb = __ldg(&g_cb[lane]);

    const int nt = (blockIdx.x < 80) ? 4 : 3;   // 80*4 + 216*3 = 968 tiles

    // ---- prologue: stage tile 0 ----
    {
        int gw = blockIdx.x;
        int b = gw / 121, rem = gw - b * 121, od = rem / 11, oh = rem - od * 11;
        const float* xb = x + (size_t)b * 221184 + (2 * od) * 576 + (2 * oh) * 24;
        float4 A0 = __ldg(reinterpret_cast<const float4*>(xb + so0));
        float4 B0 = __ldg(reinterpret_cast<const float4*>(xb + so0 + 13824));
        float4* d = reinterpret_cast<float4*>(xs2[0]);
        d[df0]     = make_float4(A0.x, B0.x, A0.y, B0.y);
        d[df0 + 1] = make_float4(A0.z, B0.z, A0.w, B0.w);
        if (h1) {
            float4 A1 = __ldg(reinterpret_cast<const float4*>(xb + so1));
            float4 B1 = __ldg(reinterpret_cast<const float4*>(xb + so1 + 13824));
            d[df1]     = make_float4(A1.x, B1.x, A1.y, B1.y);
            d[df1 + 1] = make_float4(A1.z, B1.z, A1.w, B1.w);
        }
    }
    __syncthreads();

#pragma unroll 1
    for (int it = 0; it < nt; ++it) {
        const int gw = blockIdx.x + it * 296;
        const int b = gw / 121, rem = gw - b * 121;
        const int od = rem / 11, oh = rem - od * 11;

        // ---- issue next tile's loads early (latency hides under compute) ----
        const bool more = (it + 1) < nt;
        float4 A0, B0, A1, B1;
        if (more) {
            int gn = gw + 296;
            int bn = gn / 121, rn = gn - bn * 121, odn = rn / 11, ohn = rn - odn * 11;
            const float* xb = x + (size_t)bn * 221184 + (2 * odn) * 576 + (2 * ohn) * 24;
            A0 = __ldg(reinterpret_cast<const float4*>(xb + so0));
            B0 = __ldg(reinterpret_cast<const float4*>(xb + so0 + 13824));
            if (h1) {
                A1 = __ldg(reinterpret_cast<const float4*>(xb + so1));
                B1 = __ldg(reinterpret_cast<const float4*>(xb + so1 + 13824));
            }
        }

        // ---- compute: streamed x, weights in regs ----
        const u64* xw = xs2[it & 1] + wid * 216;
        u64 acc[11];
#pragma unroll
        for (int i = 0; i < 11; ++i) acc[i] = 0ull;

#pragma unroll
        for (int rr = 0; rr < 9; ++rr) {
            const ulonglong2* rp = reinterpret_cast<const ulonglong2*>(xw + rr * 24);
            ulonglong2 tt = rp[0];
            u64 x0 = tt.x, x1 = tt.y;
#pragma unroll
            for (int ow = 0; ow < 11; ++ow) {
                ulonglong2 tn = rp[ow + 1];
                fma2(acc[ow], wr[rr * 3 + 0], x0);
                fma2(acc[ow], wr[rr * 3 + 1], x1);
                fma2(acc[ow], wr[rr * 3 + 2], tn.x);
                x0 = tn.x;
                x1 = tn.y;
            }
        }

#pragma unroll
        for (int ow = 0; ow < 11; ++ow) {
            float lo, hi;
            asm("mov.b64 {%0, %1}, %2;" : "=f"(lo), "=f"(hi) : "l"(acc[ow]));
            red[wid][ow * 32 + lane] = lo + hi;
        }
        __syncthreads();   // red ready; all reads of xs2[(it+1)&1] long done

        // ---- stage next tile ----
        if (more) {
            float4* d = reinterpret_cast<float4*>(xs2[(it + 1) & 1]);
            d[df0]     = make_float4(A0.x, B0.x, A0.y, B0.y);
            d[df0 + 1] = make_float4(A0.z, B0.z, A0.w, B0.w);
            if (h1) {
                d[df1]     = make_float4(A1.x, B1.x, A1.y, B1.y);
                d[df1 + 1] = make_float4(A1.z, B1.z, A1.w, B1.w);
            }
        }

        // ---- store current tile (co = j&31 == lane since 256%32==0) ----
        {
            float s0 = cb;
#pragma unroll
            for (int w = 0; w < 8; ++w) s0 += red[w][tid >= 352 ? 0 : tid];
            if (tid < 352)
                out[((size_t)(b * 32 + lane)) * 1331 + od * 121 + oh * 11 + (tid >> 5)] = s0;
            if (tid < 96) {
                int j = tid + 256;
                float s1 = cb;
#pragma unroll
                for (int w = 0; w < 8; ++w) s1 += red[w][j];
                out[((size_t)(b * 32 + lane)) * 1331 + od * 121 + oh * 11 + (j >> 5)] = s1;
            }
        }
        __syncthreads();   // red consumed + next x buffer visible
    }
}

extern "C" void kernel_launch(void* const* d_in, const int* in_sizes, int n_in,
                              void* d_out, int out_size) {
    const float* x     = (const float*)d_in[0];
    const float* w     = (const float*)d_in[1];
    const float* bias  = (const float*)d_in[2];
    const float* gamma = (const float*)d_in[3];
    const float* beta  = (const float*)d_in[4];
    const float* mean  = (const float*)d_in[5];
    const float* var   = (const float*)d_in[6];
    float* out = (float*)d_out;

    prep_kernel<<<(16 * 27 * 32 + 255) / 256, 256>>>(w, bias, gamma, beta, mean, var);
    conv_fused_kernel<<<296, 256>>>(x, out);
}